// round 2
// baseline (speedup 1.0000x reference)
#include <cuda_runtime.h>
#include <cstdint>

#define N_ROWS 8192
#define D_IN   1024
#define D_OUT  4096
#define GAMMA  0.01618f
#define NEG_SLOPE 0.01f
#define TOPC   128

// Scratch: device globals (allocation-free per harness rules)
__device__ float g_h[(size_t)N_ROWS * D_OUT];      // 128 MB activations
__device__ uint2 g_cand[(size_t)N_ROWS * TOPC];    // 8 MB: (float bits, idx), sorted desc by value

// ---------------------------------------------------------------------------
// Zero-fill output
// ---------------------------------------------------------------------------
__global__ void fill_kernel(float4* __restrict__ out, int n4) {
    int i = blockIdx.x * blockDim.x + threadIdx.x;
    if (i < n4) out[i] = make_float4(0.f, 0.f, 0.f, 0.f);
}

// ---------------------------------------------------------------------------
// Phase 1a: fp32 SIMT GEMM  h = leaky_relu(X @ W^T + b)
// 128x128 tile, k-tile 16, 256 threads, 8x8 per-thread micro-tile
// ---------------------------------------------------------------------------
__global__ __launch_bounds__(256) void gemm_kernel(const float* __restrict__ X,
                                                   const float* __restrict__ W,
                                                   const float* __restrict__ bias) {
    __shared__ float As[16][132];
    __shared__ float Bs[16][132];
    const int tid = threadIdx.x;
    const int tx = tid & 15, ty = tid >> 4;
    const int m0 = blockIdx.y * 128;
    const int n0 = blockIdx.x * 128;
    const int lk = (tid & 3) * 4;
    const int lr = tid >> 2;
    const float* Xp = X + (size_t)(m0 + lr) * D_IN + lk;
    const float* Wp = W + (size_t)(n0 + lr) * D_IN + lk;

    float acc[8][8];
#pragma unroll
    for (int i = 0; i < 8; i++)
#pragma unroll
        for (int j = 0; j < 8; j++) acc[i][j] = 0.f;

    for (int k0 = 0; k0 < D_IN; k0 += 16) {
#pragma unroll
        for (int h = 0; h < 2; h++) {
            float4 va = *(const float4*)(Xp + (size_t)h * 64 * D_IN + k0);
            As[lk + 0][lr + h * 64] = va.x;
            As[lk + 1][lr + h * 64] = va.y;
            As[lk + 2][lr + h * 64] = va.z;
            As[lk + 3][lr + h * 64] = va.w;
            float4 vb = *(const float4*)(Wp + (size_t)h * 64 * D_IN + k0);
            Bs[lk + 0][lr + h * 64] = vb.x;
            Bs[lk + 1][lr + h * 64] = vb.y;
            Bs[lk + 2][lr + h * 64] = vb.z;
            Bs[lk + 3][lr + h * 64] = vb.w;
        }
        __syncthreads();
#pragma unroll
        for (int kk = 0; kk < 16; kk++) {
            float4 a0 = *(const float4*)&As[kk][ty * 8];
            float4 a1 = *(const float4*)&As[kk][ty * 8 + 4];
            float4 b0 = *(const float4*)&Bs[kk][tx * 8];
            float4 b1 = *(const float4*)&Bs[kk][tx * 8 + 4];
            float a[8] = {a0.x, a0.y, a0.z, a0.w, a1.x, a1.y, a1.z, a1.w};
            float b[8] = {b0.x, b0.y, b0.z, b0.w, b1.x, b1.y, b1.z, b1.w};
#pragma unroll
            for (int i = 0; i < 8; i++)
#pragma unroll
                for (int j = 0; j < 8; j++) acc[i][j] += a[i] * b[j];
        }
        __syncthreads();
    }

#pragma unroll
    for (int i = 0; i < 8; i++) {
        const int m = m0 + ty * 8 + i;
#pragma unroll
        for (int j = 0; j < 8; j += 4) {
            float4 o;
            float* po = (float*)&o;
#pragma unroll
            for (int t = 0; t < 4; t++) {
                float v = acc[i][j + t] + bias[n0 + tx * 8 + j + t];
                po[t] = (v >= 0.f) ? v : NEG_SLOPE * v;
            }
            *(float4*)&g_h[(size_t)m * D_OUT + n0 + tx * 8 + j] = o;
        }
    }
}

// ---------------------------------------------------------------------------
// Phase 1b: per-row exact sorted top-128 (2-level radix select + bitonic)
// ---------------------------------------------------------------------------
__device__ __forceinline__ unsigned f2k(float f) {
    unsigned u = __float_as_uint(f);
    return (u & 0x80000000u) ? ~u : (u | 0x80000000u);
}
__device__ __forceinline__ float k2f(unsigned k) {
    unsigned u = (k & 0x80000000u) ? (k ^ 0x80000000u) : ~k;
    return __uint_as_float(u);
}

__global__ __launch_bounds__(256) void topc_kernel() {
    __shared__ unsigned skey[D_OUT];
    __shared__ int hist[256];
    __shared__ unsigned long long buf[256];
    __shared__ int s_b1, s_above1, s_b2, s_cnt;
    const int tid = threadIdx.x;
    const int row = blockIdx.x;

    const float4* src = (const float4*)(g_h + (size_t)row * D_OUT);
    for (int j = tid; j < D_OUT / 4; j += 256) {
        float4 v = src[j];
        skey[j * 4 + 0] = f2k(v.x);
        skey[j * 4 + 1] = f2k(v.y);
        skey[j * 4 + 2] = f2k(v.z);
        skey[j * 4 + 3] = f2k(v.w);
    }
    hist[tid] = 0;
    __syncthreads();

    // level-1 histogram on top byte
    for (int j = tid; j < D_OUT; j += 256) atomicAdd(&hist[skey[j] >> 24], 1);
    __syncthreads();
    if (tid == 0) {
        int A = 0, b;
        for (b = 255; b >= 0; b--) {
            if (A + hist[b] >= TOPC) break;
            A += hist[b];
        }
        s_b1 = b;
        s_above1 = A;   // count strictly above bin b1 (< TOPC)
    }
    __syncthreads();
    const int b1 = s_b1;
    const int above1 = s_above1;

    // level-2 histogram on next byte, only within bin b1
    hist[tid] = 0;
    __syncthreads();
    for (int j = tid; j < D_OUT; j += 256) {
        unsigned k = skey[j];
        if ((int)(k >> 24) == b1) atomicAdd(&hist[(k >> 16) & 255], 1);
    }
    __syncthreads();
    if (tid == 0) {
        int A = above1, b;
        for (b = 255; b >= 0; b--) {
            if (A + hist[b] >= TOPC) break;
            A += hist[b];
        }
        s_b2 = b;
        s_cnt = 0;
    }
    __syncthreads();
    const unsigned thr16 = ((unsigned)b1 << 8) | (unsigned)s_b2;

    // collect all elements with 16-bit key prefix >= thr16 (count in [128, ~150])
    for (int j = tid; j < D_OUT; j += 256) {
        unsigned k = skey[j];
        if ((k >> 16) >= thr16) {
            int slot = atomicAdd(&s_cnt, 1);
            if (slot < 256)
                buf[slot] = ((unsigned long long)k << 32) | (unsigned)j;
        }
    }
    __syncthreads();
    int c = s_cnt < 256 ? s_cnt : 256;
    if (tid >= c) buf[tid] = 0ull;   // pad: key 0 sorts last (smaller than any real key here)
    __syncthreads();

    // bitonic sort 256 u64, descending
    for (int k2 = 2; k2 <= 256; k2 <<= 1) {
        for (int j = k2 >> 1; j > 0; j >>= 1) {
            int ixj = tid ^ j;
            if (ixj > tid) {
                unsigned long long a = buf[tid], b = buf[ixj];
                bool desc = ((tid & k2) == 0);
                if (desc ? (a < b) : (a > b)) {
                    buf[tid] = b;
                    buf[ixj] = a;
                }
            }
            __syncthreads();
        }
    }

    if (tid < TOPC) {
        unsigned long long e = buf[tid];
        uint2 o;
        o.x = __float_as_uint(k2f((unsigned)(e >> 32)));
        o.y = (unsigned)(e & 0xffffffffu);
        g_cand[(size_t)row * TOPC + tid] = o;
    }
}

// ---------------------------------------------------------------------------
// Phase 2: serial scan (single warp)
// ---------------------------------------------------------------------------
__device__ __forceinline__ void warp_argmax(float& m, int& mi) {
#pragma unroll
    for (int off = 16; off; off >>= 1) {
        float om = __shfl_xor_sync(0xffffffffu, m, off);
        int oi = __shfl_xor_sync(0xffffffffu, mi, off);
        if (om > m || (om == m && oi < mi)) { m = om; mi = oi; }
    }
}

__device__ __noinline__ void slow_row(int row, int lane, int* lastSel,
                                      const float* phiTab, float* out) {
    // Re-evaluate all 128 candidates
    const uint2* cr = g_cand + (size_t)row * TOPC;
    float sv[4];
    int si[4];
    int undCnt = 0;
    float lastVal = 0.f;
#pragma unroll
    for (int q = 0; q < 4; q++) {
        uint2 c = cr[q * 32 + lane];
        float val = __uint_as_float(c.x);
        int idx = (int)c.y;
        int t = row - lastSel[idx] - 1;
        t = t > 63 ? 63 : t;
        float phi = phiTab[t];
        sv[q] = val * phi;
        si[q] = idx;
        undCnt += (phi == 1.0f) ? 1 : 0;
        if (q == 3) lastVal = val;
    }
    float minv = __shfl_sync(0xffffffffu, lastVal, 31);   // smallest candidate (sorted)
    int undTot = (int)__reduce_add_sync(0xffffffffu, (unsigned)undCnt);
    // Validity: >=10 undamped candidates (top-10 of s provably inside candidates),
    // OR min candidate <= 0 (all positive-h features are candidates).
    bool valid = (undTot >= 10) || (minv <= 0.0f);
    if (valid) {
        for (int it = 0; it < 10; it++) {
            float m = sv[0];
            int mq = 0;
#pragma unroll
            for (int q = 1; q < 4; q++)
                if (sv[q] > m) { m = sv[q]; mq = q; }
            int code = lane * 4 + mq;
            warp_argmax(m, code);
            if (m <= 0.0f) break;   // remaining maxima non-positive -> no binary ones
            if (lane == (code >> 2)) {
                int q = code & 3;
                int idx = si[q];
                out[(size_t)row * D_OUT + idx] = 1.0f;
                lastSel[idx] = row;
                sv[q] = -3.0e38f;
            }
            __syncwarp();
        }
    } else {
        // Exact full-row fallback (statistically never taken)
        const float* hRow = g_h + (size_t)row * D_OUT;
        for (int it = 0; it < 10; it++) {
            float m = -3.0e38f;
            int mi = 0x7fffffff;
            for (int j = lane; j < D_OUT; j += 32) {
                int ls = lastSel[j];
                if (ls == row) continue;   // already selected this row
                int t = row - ls - 1;
                t = t > 63 ? 63 : t;
                float s = hRow[j] * phiTab[t];
                if (s > m) { m = s; mi = j; }
            }
            warp_argmax(m, mi);
            if (m <= 0.0f) break;
            if (lane == 0) {
                out[(size_t)row * D_OUT + mi] = 1.0f;
                lastSel[mi] = row;
            }
            __syncwarp();
        }
    }
}

__device__ __forceinline__ void process_row(int row, uint2 cur, int lane,
                                            int* lastSel, const float* phiTab,
                                            float* out) {
    float val = __uint_as_float(cur.x);
    int idx = (int)cur.y;
    int ls = lastSel[idx];
    int t = row - ls - 1;
    t = t > 63 ? 63 : t;
    float phi = phiTab[t];
    float s = val * phi;
    bool und = (phi == 1.0f);
    unsigned bal = __ballot_sync(0xffffffffu, und);
    int p = -1;
    if (__popc(bal) >= 10) {
        unsigned b = bal;
#pragma unroll
        for (int i = 0; i < 9; i++) b &= b - 1;   // clear 9 lowest set bits
        p = __ffs(b) - 1;                          // position of 10th undamped
    }
    if (p >= 0) {
        // Fast path: top-10 of s is inside prefix lanes [0..p]. Rank by
        // pipelined shfl broadcasts (count of strictly-greater prefix values).
        int rank = 0;
        for (int j = 0; j <= p; j++) {
            float sj = __shfl_sync(0xffffffffu, s, j);
            rank += (sj > s) ? 1 : 0;
        }
        bool kept = (lane <= p) && (rank < 10) && (s > 0.0f);
        if (kept) {
            out[(size_t)row * D_OUT + idx] = 1.0f;
            lastSel[idx] = row;
        }
    } else {
        slow_row(row, lane, lastSel, phiTab, out);
    }
    __syncwarp();
}

__global__ void scan_kernel(float* __restrict__ out) {
    __shared__ int lastSel[D_OUT];
    __shared__ float phiTab[64];
    const int lane = threadIdx.x;

    for (int j = lane; j < D_OUT; j += 32) lastSel[j] = -1000;
    if (lane == 0) {
        // iterated fp32 recovery table, bit-exact vs reference's recurrence
        float p = 0.f;
        phiTab[0] = 0.f;
        for (int t = 1; t < 64; t++) {
            if (p < 1.f) p = fminf(p + GAMMA, 1.f);
            phiTab[t] = p;
        }
    }
    __syncwarp();

    // depth-3 prefetch of each row's first 32 candidates
    uint2 c0 = g_cand[(size_t)0 * TOPC + lane];
    uint2 c1 = g_cand[(size_t)1 * TOPC + lane];
    uint2 c2 = g_cand[(size_t)2 * TOPC + lane];

    for (int row = 0; row < N_ROWS; row += 3) {
        {
            uint2 cur = c0;
            int nr = row + 3 < N_ROWS ? row + 3 : N_ROWS - 1;
            c0 = g_cand[(size_t)nr * TOPC + lane];
            process_row(row, cur, lane, lastSel, phiTab, out);
        }
        if (row + 1 < N_ROWS) {
            uint2 cur = c1;
            int nr = row + 4 < N_ROWS ? row + 4 : N_ROWS - 1;
            c1 = g_cand[(size_t)nr * TOPC + lane];
            process_row(row + 1, cur, lane, lastSel, phiTab, out);
        }
        if (row + 2 < N_ROWS) {
            uint2 cur = c2;
            int nr = row + 5 < N_ROWS ? row + 5 : N_ROWS - 1;
            c2 = g_cand[(size_t)nr * TOPC + lane];
            process_row(row + 2, cur, lane, lastSel, phiTab, out);
        }
    }
}

// ---------------------------------------------------------------------------
extern "C" void kernel_launch(void* const* d_in, const int* in_sizes, int n_in,
                              void* d_out, int out_size) {
    const float* X = (const float*)d_in[0];
    const float* W = (const float*)d_in[1];
    const float* b = (const float*)d_in[2];
    float* out = (float*)d_out;

    int n4 = N_ROWS * D_OUT / 4;
    fill_kernel<<<(n4 + 255) / 256, 256>>>((float4*)out, n4);

    dim3 ggrid(D_OUT / 128, N_ROWS / 128);
    gemm_kernel<<<ggrid, 256>>>(X, W, b);

    topc_kernel<<<N_ROWS, 256>>>();

    scan_kernel<<<1, 32>>>(out);
}

// round 3
// speedup vs baseline: 1.0771x; 1.0771x over previous
#include <cuda_runtime.h>
#include <cstdint>

#define N_ROWS 8192
#define D_IN   1024
#define D_OUT  4096
#define GAMMA  0.01618f
#define NEG_SLOPE 0.01f
#define TOPC   128

// Scratch: device globals (allocation-free per harness rules)
__device__ float g_h[(size_t)N_ROWS * D_OUT];      // 128 MB activations
__device__ uint2 g_cand[(size_t)N_ROWS * TOPC];    // 8 MB: (float bits, idx), sorted desc by value

// ---------------------------------------------------------------------------
// Zero-fill output
// ---------------------------------------------------------------------------
__global__ void fill_kernel(float4* __restrict__ out, int n4) {
    int i = blockIdx.x * blockDim.x + threadIdx.x;
    if (i < n4) out[i] = make_float4(0.f, 0.f, 0.f, 0.f);
}

// ---------------------------------------------------------------------------
// Packed fp32x2 helpers (sm_103a FFMA2 path — PTX only, ptxas won't auto-fuse)
// ---------------------------------------------------------------------------
__device__ __forceinline__ unsigned long long ffma2(unsigned long long a,
                                                    unsigned long long b,
                                                    unsigned long long c) {
    unsigned long long d;
    asm("fma.rn.f32x2 %0, %1, %2, %3;" : "=l"(d) : "l"(a), "l"(b), "l"(c));
    return d;
}
__device__ __forceinline__ unsigned long long dupf(float x) {
    unsigned long long d;
    unsigned u = __float_as_uint(x);
    asm("mov.b64 %0, {%1, %1};" : "=l"(d) : "r"(u));
    return d;
}
__device__ __forceinline__ void unpack2(unsigned long long p, float& lo, float& hi) {
    unsigned a, b;
    asm("mov.b64 {%0, %1}, %2;" : "=r"(a), "=r"(b) : "l"(p));
    lo = __uint_as_float(a);
    hi = __uint_as_float(b);
}

// ---------------------------------------------------------------------------
// Phase 1a: fp32 GEMM via FFMA2  h = leaky_relu(X @ W^T + b)
// 128x128 tile, k-tile 16, 256 threads, 8x8 per-thread micro-tile.
// Accumulators paired over n (B pairs read directly as 64-bit from smem),
// A broadcast-duplicated in registers. Register prefetch of next k-tile.
// ---------------------------------------------------------------------------
__global__ __launch_bounds__(256) void gemm_kernel(const float* __restrict__ X,
                                                   const float* __restrict__ W,
                                                   const float* __restrict__ bias) {
    __shared__ float As[16][132];
    __shared__ float Bs[16][132];
    const int tid = threadIdx.x;
    const int tx = tid & 15, ty = tid >> 4;     // ty: m micro-row group, tx: n group
    const int m0 = blockIdx.y * 128;
    const int n0 = blockIdx.x * 128;
    const int lk = (tid & 3) * 4;               // k offset within tile
    const int lr = tid >> 2;                    // row 0..63
    const float* Xp = X + (size_t)(m0 + lr) * D_IN + lk;
    const float* Wp = W + (size_t)(n0 + lr) * D_IN + lk;

    // acc2[i][p]: i = m sub-row (0..7), p = n pair (0..3):
    //   p=0: n = tx*4 + {0,1},  p=1: n = tx*4 + {2,3}
    //   p=2: n = 64 + tx*4 + {0,1},  p=3: n = 64 + tx*4 + {2,3}
    unsigned long long acc2[8][4];
#pragma unroll
    for (int i = 0; i < 8; i++)
#pragma unroll
        for (int p = 0; p < 4; p++) acc2[i][p] = 0ull;

    // prefetch first k-tile into registers
    float4 pa0 = *(const float4*)(Xp + 0);
    float4 pa1 = *(const float4*)(Xp + (size_t)64 * D_IN);
    float4 pb0 = *(const float4*)(Wp + 0);
    float4 pb1 = *(const float4*)(Wp + (size_t)64 * D_IN);

    for (int k0 = 0; k0 < D_IN; k0 += 16) {
        // store prefetched tile to smem (k-major)
        As[lk + 0][lr] = pa0.x;  As[lk + 1][lr] = pa0.y;
        As[lk + 2][lr] = pa0.z;  As[lk + 3][lr] = pa0.w;
        As[lk + 0][lr + 64] = pa1.x;  As[lk + 1][lr + 64] = pa1.y;
        As[lk + 2][lr + 64] = pa1.z;  As[lk + 3][lr + 64] = pa1.w;
        Bs[lk + 0][lr] = pb0.x;  Bs[lk + 1][lr] = pb0.y;
        Bs[lk + 2][lr] = pb0.z;  Bs[lk + 3][lr] = pb0.w;
        Bs[lk + 0][lr + 64] = pb1.x;  Bs[lk + 1][lr + 64] = pb1.y;
        Bs[lk + 2][lr + 64] = pb1.z;  Bs[lk + 3][lr + 64] = pb1.w;
        __syncthreads();

        // issue next tile's global loads (latency hidden under compute)
        if (k0 + 16 < D_IN) {
            const int kn = k0 + 16;
            pa0 = *(const float4*)(Xp + kn);
            pa1 = *(const float4*)(Xp + (size_t)64 * D_IN + kn);
            pb0 = *(const float4*)(Wp + kn);
            pb1 = *(const float4*)(Wp + (size_t)64 * D_IN + kn);
        }

#pragma unroll
        for (int kk = 0; kk < 16; kk++) {
            // B pairs: 2x 16B conflict-free loads (lane stride 16B)
            const ulonglong2 b01 = *(const ulonglong2*)&Bs[kk][tx * 4];
            const ulonglong2 b23 = *(const ulonglong2*)&Bs[kk][64 + tx * 4];
            // A scalars for this thread's 8 m-rows (broadcast loads)
            const float4 a0 = *(const float4*)&As[kk][ty * 8];
            const float4 a1 = *(const float4*)&As[kk][ty * 8 + 4];
            const float av[8] = {a0.x, a0.y, a0.z, a0.w, a1.x, a1.y, a1.z, a1.w};
#pragma unroll
            for (int i = 0; i < 8; i++) {
                const unsigned long long ad = dupf(av[i]);
                acc2[i][0] = ffma2(ad, b01.x, acc2[i][0]);
                acc2[i][1] = ffma2(ad, b01.y, acc2[i][1]);
                acc2[i][2] = ffma2(ad, b23.x, acc2[i][2]);
                acc2[i][3] = ffma2(ad, b23.y, acc2[i][3]);
            }
        }
        __syncthreads();
    }

    // epilogue: bias + leaky_relu, store
    const float4 bv0 = *(const float4*)&bias[n0 + tx * 4];
    const float4 bv1 = *(const float4*)&bias[n0 + 64 + tx * 4];
    const float bb[8] = {bv0.x, bv0.y, bv0.z, bv0.w, bv1.x, bv1.y, bv1.z, bv1.w};
#pragma unroll
    for (int i = 0; i < 8; i++) {
        const int m = m0 + ty * 8 + i;
#pragma unroll
        for (int c = 0; c < 2; c++) {
            float f0, f1, f2, f3;
            unpack2(acc2[i][c * 2 + 0], f0, f1);
            unpack2(acc2[i][c * 2 + 1], f2, f3);
            float4 o;
            float v;
            v = f0 + bb[c * 4 + 0]; o.x = (v >= 0.f) ? v : NEG_SLOPE * v;
            v = f1 + bb[c * 4 + 1]; o.y = (v >= 0.f) ? v : NEG_SLOPE * v;
            v = f2 + bb[c * 4 + 2]; o.z = (v >= 0.f) ? v : NEG_SLOPE * v;
            v = f3 + bb[c * 4 + 3]; o.w = (v >= 0.f) ? v : NEG_SLOPE * v;
            *(float4*)&g_h[(size_t)m * D_OUT + n0 + c * 64 + tx * 4] = o;
        }
    }
}

// ---------------------------------------------------------------------------
// Phase 1b: per-row exact sorted top-128 (2-level radix select + bitonic)
// ---------------------------------------------------------------------------
__device__ __forceinline__ unsigned f2k(float f) {
    unsigned u = __float_as_uint(f);
    return (u & 0x80000000u) ? ~u : (u | 0x80000000u);
}
__device__ __forceinline__ float k2f(unsigned k) {
    unsigned u = (k & 0x80000000u) ? (k ^ 0x80000000u) : ~k;
    return __uint_as_float(u);
}

__global__ __launch_bounds__(256) void topc_kernel() {
    __shared__ unsigned skey[D_OUT];
    __shared__ int hist[256];
    __shared__ unsigned long long buf[256];
    __shared__ int s_b1, s_above1, s_b2, s_cnt;
    const int tid = threadIdx.x;
    const int row = blockIdx.x;

    const float4* src = (const float4*)(g_h + (size_t)row * D_OUT);
    for (int j = tid; j < D_OUT / 4; j += 256) {
        float4 v = src[j];
        skey[j * 4 + 0] = f2k(v.x);
        skey[j * 4 + 1] = f2k(v.y);
        skey[j * 4 + 2] = f2k(v.z);
        skey[j * 4 + 3] = f2k(v.w);
    }
    hist[tid] = 0;
    __syncthreads();

    for (int j = tid; j < D_OUT; j += 256) atomicAdd(&hist[skey[j] >> 24], 1);
    __syncthreads();
    if (tid == 0) {
        int A = 0, b;
        for (b = 255; b >= 0; b--) {
            if (A + hist[b] >= TOPC) break;
            A += hist[b];
        }
        s_b1 = b;
        s_above1 = A;
    }
    __syncthreads();
    const int b1 = s_b1;
    const int above1 = s_above1;

    hist[tid] = 0;
    __syncthreads();
    for (int j = tid; j < D_OUT; j += 256) {
        unsigned k = skey[j];
        if ((int)(k >> 24) == b1) atomicAdd(&hist[(k >> 16) & 255], 1);
    }
    __syncthreads();
    if (tid == 0) {
        int A = above1, b;
        for (b = 255; b >= 0; b--) {
            if (A + hist[b] >= TOPC) break;
            A += hist[b];
        }
        s_b2 = b;
        s_cnt = 0;
    }
    __syncthreads();
    const unsigned thr16 = ((unsigned)b1 << 8) | (unsigned)s_b2;

    for (int j = tid; j < D_OUT; j += 256) {
        unsigned k = skey[j];
        if ((k >> 16) >= thr16) {
            int slot = atomicAdd(&s_cnt, 1);
            if (slot < 256)
                buf[slot] = ((unsigned long long)k << 32) | (unsigned)j;
        }
    }
    __syncthreads();
    int c = s_cnt < 256 ? s_cnt : 256;
    if (tid >= c) buf[tid] = 0ull;
    __syncthreads();

    for (int k2 = 2; k2 <= 256; k2 <<= 1) {
        for (int j = k2 >> 1; j > 0; j >>= 1) {
            int ixj = tid ^ j;
            if (ixj > tid) {
                unsigned long long a = buf[tid], b = buf[ixj];
                bool desc = ((tid & k2) == 0);
                if (desc ? (a < b) : (a > b)) {
                    buf[tid] = b;
                    buf[ixj] = a;
                }
            }
            __syncthreads();
        }
    }

    if (tid < TOPC) {
        unsigned long long e = buf[tid];
        uint2 o;
        o.x = __float_as_uint(k2f((unsigned)(e >> 32)));
        o.y = (unsigned)(e & 0xffffffffu);
        g_cand[(size_t)row * TOPC + tid] = o;
    }
}

// ---------------------------------------------------------------------------
// Phase 2: serial scan (single warp)
// ---------------------------------------------------------------------------
__device__ __forceinline__ void warp_argmax(float& m, int& mi) {
#pragma unroll
    for (int off = 16; off; off >>= 1) {
        float om = __shfl_xor_sync(0xffffffffu, m, off);
        int oi = __shfl_xor_sync(0xffffffffu, mi, off);
        if (om > m || (om == m && oi < mi)) { m = om; mi = oi; }
    }
}

__device__ __noinline__ void slow_row(int row, int lane, int* lastSel,
                                      const float* phiTab, float* out) {
    const uint2* cr = g_cand + (size_t)row * TOPC;
    float sv[4];
    int si[4];
    int undCnt = 0;
    float lastVal = 0.f;
#pragma unroll
    for (int q = 0; q < 4; q++) {
        uint2 c = cr[q * 32 + lane];
        float val = __uint_as_float(c.x);
        int idx = (int)c.y;
        int t = row - lastSel[idx] - 1;
        t = t > 63 ? 63 : t;
        float phi = phiTab[t];
        sv[q] = val * phi;
        si[q] = idx;
        undCnt += (phi == 1.0f) ? 1 : 0;
        if (q == 3) lastVal = val;
    }
    float minv = __shfl_sync(0xffffffffu, lastVal, 31);
    int undTot = (int)__reduce_add_sync(0xffffffffu, (unsigned)undCnt);
    bool valid = (undTot >= 10) || (minv <= 0.0f);
    if (valid) {
        for (int it = 0; it < 10; it++) {
            float m = sv[0];
            int mq = 0;
#pragma unroll
            for (int q = 1; q < 4; q++)
                if (sv[q] > m) { m = sv[q]; mq = q; }
            int code = lane * 4 + mq;
            warp_argmax(m, code);
            if (m <= 0.0f) break;
            if (lane == (code >> 2)) {
                int q = code & 3;
                int idx = si[q];
                out[(size_t)row * D_OUT + idx] = 1.0f;
                lastSel[idx] = row;
                sv[q] = -3.0e38f;
            }
            __syncwarp();
        }
    } else {
        const float* hRow = g_h + (size_t)row * D_OUT;
        for (int it = 0; it < 10; it++) {
            float m = -3.0e38f;
            int mi = 0x7fffffff;
            for (int j = lane; j < D_OUT; j += 32) {
                int ls = lastSel[j];
                if (ls == row) continue;
                int t = row - ls - 1;
                t = t > 63 ? 63 : t;
                float s = hRow[j] * phiTab[t];
                if (s > m) { m = s; mi = j; }
            }
            warp_argmax(m, mi);
            if (m <= 0.0f) break;
            if (lane == 0) {
                out[(size_t)row * D_OUT + mi] = 1.0f;
                lastSel[mi] = row;
            }
            __syncwarp();
        }
    }
}

__device__ __forceinline__ void process_row(int row, uint2 cur, int lane,
                                            int* lastSel, const float* phiTab,
                                            float* out) {
    float val = __uint_as_float(cur.x);
    int idx = (int)cur.y;
    int ls = lastSel[idx];
    int t = row - ls - 1;
    t = t > 63 ? 63 : t;
    float phi = phiTab[t];
    float s = val * phi;
    bool und = (phi == 1.0f);
    unsigned bal = __ballot_sync(0xffffffffu, und);
    int p = -1;
    if (__popc(bal) >= 10) {
        unsigned b = bal;
#pragma unroll
        for (int i = 0; i < 9; i++) b &= b - 1;
        p = __ffs(b) - 1;
    }
    if (p >= 0) {
        int rank = 0;
        for (int j = 0; j <= p; j++) {
            float sj = __shfl_sync(0xffffffffu, s, j);
            rank += (sj > s) ? 1 : 0;
        }
        bool kept = (lane <= p) && (rank < 10) && (s > 0.0f);
        if (kept) {
            out[(size_t)row * D_OUT + idx] = 1.0f;
            lastSel[idx] = row;
        }
    } else {
        slow_row(row, lane, lastSel, phiTab, out);
    }
    __syncwarp();
}

__global__ void scan_kernel(float* __restrict__ out) {
    __shared__ int lastSel[D_OUT];
    __shared__ float phiTab[64];
    const int lane = threadIdx.x;

    for (int j = lane; j < D_OUT; j += 32) lastSel[j] = -1000;
    if (lane == 0) {
        float p = 0.f;
        phiTab[0] = 0.f;
        for (int t = 1; t < 64; t++) {
            if (p < 1.f) p = fminf(p + GAMMA, 1.f);
            phiTab[t] = p;
        }
    }
    __syncwarp();

    uint2 c0 = g_cand[(size_t)0 * TOPC + lane];
    uint2 c1 = g_cand[(size_t)1 * TOPC + lane];
    uint2 c2 = g_cand[(size_t)2 * TOPC + lane];

    for (int row = 0; row < N_ROWS; row += 3) {
        {
            uint2 cur = c0;
            int nr = row + 3 < N_ROWS ? row + 3 : N_ROWS - 1;
            c0 = g_cand[(size_t)nr * TOPC + lane];
            process_row(row, cur, lane, lastSel, phiTab, out);
        }
        if (row + 1 < N_ROWS) {
            uint2 cur = c1;
            int nr = row + 4 < N_ROWS ? row + 4 : N_ROWS - 1;
            c1 = g_cand[(size_t)nr * TOPC + lane];
            process_row(row + 1, cur, lane, lastSel, phiTab, out);
        }
        if (row + 2 < N_ROWS) {
            uint2 cur = c2;
            int nr = row + 5 < N_ROWS ? row + 5 : N_ROWS - 1;
            c2 = g_cand[(size_t)nr * TOPC + lane];
            process_row(row + 2, cur, lane, lastSel, phiTab, out);
        }
    }
}

// ---------------------------------------------------------------------------
extern "C" void kernel_launch(void* const* d_in, const int* in_sizes, int n_in,
                              void* d_out, int out_size) {
    const float* X = (const float*)d_in[0];
    const float* W = (const float*)d_in[1];
    const float* b = (const float*)d_in[2];
    float* out = (float*)d_out;

    int n4 = N_ROWS * D_OUT / 4;
    fill_kernel<<<(n4 + 255) / 256, 256>>>((float4*)out, n4);

    dim3 ggrid(D_OUT / 128, N_ROWS / 128);
    gemm_kernel<<<ggrid, 256>>>(X, W, b);

    topc_kernel<<<N_ROWS, 256>>>();

    scan_kernel<<<1, 32>>>(out);
}